// round 9
// baseline (speedup 1.0000x reference)
#include <cuda_runtime.h>
#include <cuda_fp16.h>
#include <math.h>

#define B   8
#define C1  256
#define HW1 4096
#define C2  512
#define HW2 1024

#define TPB  256

#define CCH  8                  // channels per tile (== warps per block)
#define HWCH 1024               // hw elements per tile (256 thr * float4)
#define NC1  (C1 / CCH)         // 32
#define NH1  (HW1 / HWCH)       // 4
#define NC2  (C2 / CCH)         // 64
#define NH2  (HW2 / HWCH)       // 1
#define TILES1 (B * NC1 * NH1)  // 1024
#define TILES2 (B * NC2 * NH2)  // 512
#define TILESTOT (TILES1 + TILES2)

#define P2CH 16
#define P2B1 (B * (C1 / P2CH) * (HW1 / HWCH))   // 512
#define P2B2 (B * (C2 / P2CH) * (HW2 / HWCH))   // 256
#define P2TOT (P2B1 + P2B2)                     // 768

#define MAXBLK 1024

// ---------------- scratch ----------------------------------------------------
__device__ __align__(128) float g_Gs1p[2][NC1][B * HW1];   // partials
__device__ __align__(128) float g_Gs2p[2][NC2][B * HW2];
__device__ __align__(128) float g_Gc1p[2][B * C1][NH1];
__device__ __align__(128) float g_Gc2p[2][B * C2][NH2];

__device__ __align__(128) float g_Gs1[2][B * HW1];         // compact spatial sums
__device__ __align__(128) float g_Gs2[2][B * HW2];

__device__ __align__(128) __half g_d1[B * C1 * HW1];       // fp16 (s-t) stash
__device__ __align__(128) __half g_d2[B * C2 * HW2];

__device__ __align__(128) float g_Ms1[B * HW1];
__device__ __align__(128) float g_Mc1[B * C1];
__device__ __align__(128) float g_Ms2[B * HW2];
__device__ __align__(128) float g_Mc2[B * C2];

__device__ double g_latpart[16];
__device__ float  g_p2a[MAXBLK];                 // level-1 slam partials
__device__ float  g_p2b[MAXBLK];                 // level-2 slam partials
__device__ unsigned g_next1 = 0, g_next2 = 0;
__device__ unsigned g_arrive = 0, g_gen = 0;     // sense-reversing barrier

union F2D { float2 f2; double d; };

// ---------------- helpers -----------------------------------------------------
__device__ __forceinline__ float blockReduceSum(float v) {
    __shared__ float sh[8];
    int lane = threadIdx.x & 31, warp = threadIdx.x >> 5;
#pragma unroll
    for (int o = 16; o > 0; o >>= 1) v += __shfl_down_sync(0xffffffffu, v, o);
    __syncthreads();
    if (lane == 0) sh[warp] = v;
    __syncthreads();
    if (threadIdx.x == 0) {
        float r = 0.f;
#pragma unroll
        for (int w = 0; w < TPB / 32; w++) r += sh[w];
        sh[0] = r;
    }
    __syncthreads();
    return sh[0];
}

__device__ __forceinline__ float blockReduceMax(float v) {
    __shared__ float sh[8];
    int lane = threadIdx.x & 31, warp = threadIdx.x >> 5;
#pragma unroll
    for (int o = 16; o > 0; o >>= 1) v = fmaxf(v, __shfl_down_sync(0xffffffffu, v, o));
    __syncthreads();
    if (lane == 0) sh[warp] = v;
    __syncthreads();
    if (threadIdx.x == 0) {
        float r = sh[0];
#pragma unroll
        for (int w = 1; w < TPB / 32; w++) r = fmaxf(r, sh[w]);
        sh[0] = r;
    }
    __syncthreads();
    return sh[0];
}

// sense-reversing grid barrier: self-resetting, safe across graph replays
__device__ __forceinline__ void gridBarrier(int nblocks) {
    __syncthreads();
    if (threadIdx.x == 0) {
        __threadfence();
        unsigned gen = *(volatile unsigned*)&g_gen;   // read BEFORE arriving
        unsigned old = atomicAdd(&g_arrive, 1u);
        if (old == (unsigned)nblocks - 1u) {
            g_arrive = 0;
            __threadfence();
            atomicAdd(&g_gen, 1u);                    // release
        } else {
            while (*(volatile unsigned*)&g_gen == gen) __nanosleep(64);
        }
        __threadfence();
    }
    __syncthreads();
}

__device__ __forceinline__ void discard_l2(const void* p) {
    unsigned long long g;
    asm("cvta.to.global.u64 %0, %1;" : "=l"(g) : "l"(p));
    asm volatile("discard.global.L2 [%0], 128;" :: "l"(g) : "memory");
}

// ---------------- phase 1: streaming tile ------------------------------------
template <int Cc, int HWc, int NC, int NH>
__device__ __forceinline__ void pass1_tile(
    const float* __restrict__ s, const float* __restrict__ t,
    __half* __restrict__ dst,
    float* __restrict__ Gsp_s, float* __restrict__ Gsp_t,
    float* __restrict__ Gcp_s, float* __restrict__ Gcp_t,
    float2 (*stage)[TPB], int tile)
{
    const int tid = threadIdx.x;
    const int lane = tid & 31, warp = tid >> 5;
    const int b  = tile / (NC * NH);
    const int r  = tile % (NC * NH);
    const int cc = r / NH;
    const int hh = r % NH;
    const int hwbase = hh * HWCH;
    const int c0 = cc * CCH;

    const size_t base4 = (((size_t)b * Cc + c0) * HWc + hwbase) / 4;
    const float4* ps = (const float4*)s + base4 + tid;
    const float4* pt = (const float4*)t + base4 + tid;
    uint2* pd = (uint2*)dst + base4 + tid;
    constexpr int STR4 = HWc / 4;

    float4 as = make_float4(0.f, 0.f, 0.f, 0.f);
    float4 at = make_float4(0.f, 0.f, 0.f, 0.f);

#pragma unroll
    for (int ci = 0; ci < CCH; ci++) {
        float4 vs = __ldcs(&ps[(size_t)ci * STR4]);   // evict-first
        float4 vt = __ldcs(&pt[(size_t)ci * STR4]);

        __half2 h01 = __floats2half2_rn(vs.x - vt.x, vs.y - vt.y);
        __half2 h23 = __floats2half2_rn(vs.z - vt.z, vs.w - vt.w);
        uint2 u;
        u.x = *reinterpret_cast<const unsigned*>(&h01);
        u.y = *reinterpret_cast<const unsigned*>(&h23);
        pd[(size_t)ci * STR4] = u;

        vs.x = fabsf(vs.x); vs.y = fabsf(vs.y); vs.z = fabsf(vs.z); vs.w = fabsf(vs.w);
        vt.x = fabsf(vt.x); vt.y = fabsf(vt.y); vt.z = fabsf(vt.z); vt.w = fabsf(vt.w);
        as.x += vs.x; as.y += vs.y; as.z += vs.z; as.w += vs.w;
        at.x += vt.x; at.y += vt.y; at.z += vt.z; at.w += vt.w;

        stage[ci][tid] = make_float2((vs.x + vs.y) + (vs.z + vs.w),
                                     (vt.x + vt.y) + (vt.z + vt.w));
    }

    float4* os = (float4*)(Gsp_s + (size_t)cc * (B * HWc) + b * HWc + hwbase) + tid;
    float4* ot = (float4*)(Gsp_t + (size_t)cc * (B * HWc) + b * HWc + hwbase) + tid;
    *os = as;
    *ot = at;

    __syncthreads();

    float2 acc = make_float2(0.f, 0.f);
#pragma unroll
    for (int k = 0; k < TPB / 32; k++) {
        float2 v = stage[warp][lane + 32 * k];
        acc.x += v.x; acc.y += v.y;
    }
    F2D u2; u2.f2 = acc;
#pragma unroll
    for (int o = 16; o > 0; o >>= 1) {
        F2D v; v.d = __shfl_down_sync(0xffffffffu, u2.d, o);
        u2.f2.x += v.f2.x; u2.f2.y += v.f2.y;
    }
    if (lane == 0) {
        int idx = (b * Cc + c0 + warp) * NH + hh;
        Gcp_s[idx] = u2.f2.x;
        Gcp_t[idx] = u2.f2.y;
    }
}

// ---------------- softmax (compact inputs, 256 threads) -----------------------
template <int Cc, int HWc, int NPART>
__device__ void softmax_level(
    const float* __restrict__ Gs_s, const float* __restrict__ Gs_t,
    const float* __restrict__ Gcp_s, const float* __restrict__ Gcp_t,
    float* __restrict__ Ms, float* __restrict__ Mc,
    int b, float* zbuf, double* latout)
{
    const int tid = threadIdx.x;

    float latp = 0.f, mx = -INFINITY;
    for (int i = tid; i < HWc; i += TPB) {
        float ss = Gs_s[b * HWc + i];
        float st = Gs_t[b * HWc + i];
        float d = ss - st;
        latp += d * d;
        float z = (ss + st) * (2.0f / (float)Cc);   // /C then /T (T=0.5)
        zbuf[i] = z;
        mx = fmaxf(mx, z);
    }
    float m = blockReduceMax(mx);
    float se = 0.f;
    for (int i = tid; i < HWc; i += TPB) {
        float e = __expf(zbuf[i] - m);
        zbuf[i] = e;
        se += e;
    }
    float S = blockReduceSum(se);
    float sc = (float)HWc / S;
    for (int i = tid; i < HWc; i += TPB) Ms[b * HWc + i] = zbuf[i] * sc;
    float lat_s = blockReduceSum(latp);

    float latc = 0.f, mxc = -INFINITY;
    for (int i = tid; i < Cc; i += TPB) {
        float cs = 0.f, ct = 0.f;
#pragma unroll
        for (int k = 0; k < NPART; k++) {
            cs += Gcp_s[(size_t)(b * Cc + i) * NPART + k];
            ct += Gcp_t[(size_t)(b * Cc + i) * NPART + k];
        }
        float d = cs - ct;
        latc += d * d;
        float z = (cs + ct) * (2.0f / (float)HWc);
        zbuf[i] = z;
        mxc = fmaxf(mxc, z);
    }
    float m2 = blockReduceMax(mxc);
    float sec = 0.f;
    for (int i = tid; i < Cc; i += TPB) {
        float e = __expf(zbuf[i] - m2);
        zbuf[i] = e;
        sec += e;
    }
    float Sc = blockReduceSum(sec);
    float scc = (float)Cc / Sc;
    for (int i = tid; i < Cc; i += TPB) Mc[b * Cc + i] = zbuf[i] * scc;
    float lat_c = blockReduceSum(latc);

    if (tid == 0)
        *latout = (double)lat_s / ((double)Cc * (double)Cc) +
                  (double)lat_c / ((double)HWc * (double)HWc);
}

// ---------------- pass 2 item (NO discard here) --------------------------------
template <int Cc, int HWc>
__device__ __forceinline__ float pass2_item(
    const __half* __restrict__ dsrc,
    const float* __restrict__ Ms, const float* __restrict__ Mc,
    int b, int c0, int hwbase)
{
    const int tid = threadIdx.x;
    float4 ms = *(const float4*)(Ms + (size_t)b * HWc + hwbase + tid * 4);

    float acc = 0.f;
#pragma unroll
    for (int ci = 0; ci < P2CH; ci++) {
        const int c = c0 + ci;
        const uint2* p = (const uint2*)dsrc +
                         (((size_t)b * Cc + c) * HWc + hwbase) / 4 + tid;
        uint2 v = *p;
        float2 f0 = __half22float2(*reinterpret_cast<const __half2*>(&v.x));
        float2 f1 = __half22float2(*reinterpret_cast<const __half2*>(&v.y));
        float e = f0.x * f0.x * ms.x + f0.y * f0.y * ms.y
                + f1.x * f1.x * ms.z + f1.y * f1.y * ms.w;
        acc += e * Mc[b * Cc + c];
    }
    return acc;
}

// ---------------- the one persistent kernel ------------------------------------
__global__ void __launch_bounds__(TPB, 5)
fused_kernel(const float* __restrict__ s1, const float* __restrict__ t1,
             const float* __restrict__ s2, const float* __restrict__ t2,
             float* out, int out_size, int nblocks)
{
    __shared__ __align__(16) char sh_raw[CCH * TPB * sizeof(float2)];   // 16 KB
    float2 (*stage)[TPB] = reinterpret_cast<float2(*)[TPB]>(sh_raw);
    float* zbuf = reinterpret_cast<float*>(sh_raw);
    __shared__ int sh_item;

    const int tid = threadIdx.x;
    const int bid = blockIdx.x;
    const unsigned NT = (unsigned)nblocks * TPB;
    const unsigned gt = (unsigned)bid * TPB + tid;

    // ===== phase 1: streaming pass (dynamic queue, no wave quantization) =====
    for (;;) {
        if (tid == 0) sh_item = atomicAdd(&g_next1, 1u);
        __syncthreads();                       // broadcast + protects stage reuse
        int tile = sh_item;
        if (tile >= TILESTOT) break;
        if (tile < TILES1)
            pass1_tile<C1, HW1, NC1, NH1>(s1, t1, g_d1,
                &g_Gs1p[0][0][0], &g_Gs1p[1][0][0],
                &g_Gc1p[0][0][0], &g_Gc1p[1][0][0], stage, tile);
        else
            pass1_tile<C2, HW2, NC2, NH2>(s2, t2, g_d2,
                &g_Gs2p[0][0][0], &g_Gs2p[1][0][0],
                &g_Gc2p[0][0][0], &g_Gc2p[1][0][0], stage, tile - TILES1);
    }
    gridBarrier(nblocks);

    // ===== phase 1.5: reduce Gs partials -> compact (reads only; NO discard) ===
    for (unsigned i = gt; i < B * HW1; i += NT) {
        float ss = 0.f, st = 0.f;
#pragma unroll
        for (int p = 0; p < NC1; p++) { ss += g_Gs1p[0][p][i]; st += g_Gs1p[1][p][i]; }
        g_Gs1[0][i] = ss; g_Gs1[1][i] = st;
    }
    for (unsigned i = gt; i < B * HW2; i += NT) {
        float ss = 0.f, st = 0.f;
#pragma unroll
        for (int p = 0; p < NC2; p++) { ss += g_Gs2p[0][p][i]; st += g_Gs2p[1][p][i]; }
        g_Gs2[0][i] = ss; g_Gs2[1][i] = st;
    }
    gridBarrier(nblocks);   // all partial reads complete here

    // ===== phase 2: softmax on 16 blocks; others discard consumed partials =====
    if (bid < 16) {
        if (bid < B)
            softmax_level<C1, HW1, NH1>(g_Gs1[0], g_Gs1[1],
                &g_Gc1p[0][0][0], &g_Gc1p[1][0][0],
                g_Ms1, g_Mc1, bid, zbuf, &g_latpart[bid]);
        else
            softmax_level<C2, HW2, NH2>(g_Gs2[0], g_Gs2[1],
                &g_Gc2p[0][0][0], &g_Gc2p[1][0][0],
                g_Ms2, g_Mc2, bid - B, zbuf, &g_latpart[bid]);
    } else {
        // Gs partials fully consumed (barrier above): discard dirty lines so
        // they never write back to DRAM. Disjoint from softmax's data.
        const unsigned gt2 = (unsigned)(bid - 16) * TPB + tid;
        const unsigned NT2 = (unsigned)(nblocks - 16) * TPB;
        const float* base1 = &g_Gs1p[0][0][0];
        unsigned nl1 = 2u * NC1 * (B * HW1 / 32);
        for (unsigned L = gt2; L < nl1; L += NT2) discard_l2(base1 + (size_t)L * 32);
        const float* base2 = &g_Gs2p[0][0][0];
        unsigned nl2 = 2u * NC2 * (B * HW2 / 32);
        for (unsigned L = gt2; L < nl2; L += NT2) discard_l2(base2 + (size_t)L * 32);
    }
    gridBarrier(nblocks);

    // ===== phase 3: weighted SSE over fp16 stash (dynamic queue) =====
    float acc1 = 0.f, acc2 = 0.f;
    for (;;) {
        if (tid == 0) sh_item = atomicAdd(&g_next2, 1u);
        __syncthreads();
        int item = sh_item;
        if (item >= P2TOT) break;
        if (item < P2B1) {
            int b = item / ((C1 / P2CH) * (HW1 / HWCH));
            int r = item % ((C1 / P2CH) * (HW1 / HWCH));
            int c0 = (r / (HW1 / HWCH)) * P2CH;
            int hwbase = (r % (HW1 / HWCH)) * HWCH;
            acc1 += pass2_item<C1, HW1>(g_d1, g_Ms1, g_Mc1, b, c0, hwbase);
        } else {
            int id = item - P2B1;
            int b = id / (C2 / P2CH);
            int c0 = (id % (C2 / P2CH)) * P2CH;
            acc2 += pass2_item<C2, HW2>(g_d2, g_Ms2, g_Mc2, b, c0, 0);
        }
    }
    float bl1 = blockReduceSum(acc1);
    float bl2 = blockReduceSum(acc2);
    if (tid == 0) { g_p2a[bid] = bl1; g_p2b[bid] = bl2; }
    gridBarrier(nblocks);   // all stash reads + partial writes complete here

    // ===== phase 4: stash discard (all blocks) + final combine (block 0) =====
    {
        const __half* d1 = g_d1;
        unsigned nl1 = (unsigned)(B * C1 * HW1 / 64);
        for (unsigned L = gt; L < nl1; L += NT) discard_l2(d1 + (size_t)L * 64);
        const __half* d2 = g_d2;
        unsigned nl2 = (unsigned)(B * C2 * HW2 / 64);
        for (unsigned L = gt; L < nl2; L += NT) discard_l2(d2 + (size_t)L * 64);
    }

    if (bid == 0) {
        double a1 = 0.0, a2 = 0.0;
        for (int i = tid; i < nblocks; i += TPB) {
            a1 += (double)g_p2a[i];
            a2 += (double)g_p2b[i];
        }
        __shared__ double sh1[8], sh2[8];
        int lane = tid & 31, warp = tid >> 5;
#pragma unroll
        for (int o = 16; o > 0; o >>= 1) {
            a1 += __shfl_down_sync(0xffffffffu, a1, o);
            a2 += __shfl_down_sync(0xffffffffu, a2, o);
        }
        if (lane == 0) { sh1[warp] = a1; sh2[warp] = a2; }
        __syncthreads();
        if (tid == 0) {
            double s1 = 0.0, s2 = 0.0;
            for (int w = 0; w < TPB / 32; w++) { s1 += sh1[w]; s2 += sh2[w]; }
            double lat = 0.0;
            for (int i = 0; i < 16; i++) lat += g_latpart[i];
            double lam = sqrt(s1) + sqrt(s2);
            double att = (4e-4 * lat + 2e-2 * lam) / (double)B / 2.0;   // ATT=1
            out[0] = (float)(att * (double)B);
            if (out_size > 1) out[1] = (float)att;
            g_next1 = 0;     // reset queues for next graph replay
            g_next2 = 0;     // (barrier counters are self-resetting)
        }
    }
}

// ---------------- launch --------------------------------------------------------
extern "C" void kernel_launch(void* const* d_in, const int* in_sizes, int n_in,
                              void* d_out, int out_size) {
    const float* stu1 = (const float*)d_in[1];
    const float* tea1 = (const float*)d_in[2];
    const float* stu2 = (const float*)d_in[3];
    const float* tea2 = (const float*)d_in[4];
    float* out = (float*)d_out;

    int numSMs = 0, occ = 0;
    cudaDeviceGetAttribute(&numSMs, cudaDevAttrMultiProcessorCount, 0);
    cudaOccupancyMaxActiveBlocksPerMultiprocessor(&occ, fused_kernel, TPB, 0);
    int nblocks = numSMs * occ;
    if (nblocks > MAXBLK) nblocks = MAXBLK;
    if (nblocks < 17) nblocks = 17;   // need >16 for the phase-2 split

    fused_kernel<<<nblocks, TPB>>>(stu1, tea1, stu2, tea2, out, out_size, nblocks);
}

// round 10
// speedup vs baseline: 1.2764x; 1.2764x over previous
#include <cuda_runtime.h>
#include <cuda_fp16.h>
#include <math.h>

#define B   8
#define C1  256
#define HW1 4096
#define C2  512
#define HW2 1024

#define TPB  256
#define STPB 1024

#define CCH  8                  // channels per tile (== warps per block)
#define HWCH 1024               // hw elements per tile (256 thr * float4)
#define NC1  (C1 / CCH)         // 32
#define NH1  (HW1 / HWCH)       // 4
#define NC2  (C2 / CCH)         // 64
#define NH2  (HW2 / HWCH)       // 1
#define TILES1 (B * NC1 * NH1)  // 1024
#define TILES2 (B * NC2 * NH2)  // 512

#define P2CH 16
#define P2B1 (B * (C1 / P2CH) * (HW1 / HWCH))   // 512
#define P2B2 (B * (C2 / P2CH) * (HW2 / HWCH))   // 256
#define P2TOT (P2B1 + P2B2)                     // 768

#define RGRID 640               // reduce kernel blocks

// ---------------- scratch ----------------------------------------------------
__device__ __align__(128) float g_Gs1p[2][NC1][B * HW1];   // partials
__device__ __align__(128) float g_Gs2p[2][NC2][B * HW2];
__device__ __align__(128) float g_Gc1p[2][B * C1][NH1];
__device__ __align__(128) float g_Gc2p[2][B * C2][NH2];

__device__ __align__(128) float g_Gs1[2][B * HW1];         // compact sums
__device__ __align__(128) float g_Gs2[2][B * HW2];

__device__ __align__(128) __half g_d1[B * C1 * HW1];       // fp16 (s-t) stash
__device__ __align__(128) __half g_d2[B * C2 * HW2];

__device__ __align__(128) float g_Ms1[B * HW1];
__device__ __align__(128) float g_Mc1[B * C1];
__device__ __align__(128) float g_Ms2[B * HW2];
__device__ __align__(128) float g_Mc2[B * C2];

__device__ double g_latpart[16];
__device__ float  g_p2[P2TOT];
__device__ unsigned g_count = 0;

union F2D { float2 f2; double d; };

// ---------------- reduce helpers ---------------------------------------------
__device__ __forceinline__ float blockReduceSum(float v) {
    __shared__ float sh[32];
    int lane = threadIdx.x & 31, warp = threadIdx.x >> 5;
    int nw = blockDim.x >> 5;
#pragma unroll
    for (int o = 16; o > 0; o >>= 1) v += __shfl_down_sync(0xffffffffu, v, o);
    __syncthreads();
    if (lane == 0) sh[warp] = v;
    __syncthreads();
    if (threadIdx.x == 0) {
        float r = 0.f;
        for (int w = 0; w < nw; w++) r += sh[w];
        sh[0] = r;
    }
    __syncthreads();
    return sh[0];
}

__device__ __forceinline__ float blockReduceMax(float v) {
    __shared__ float sh[32];
    int lane = threadIdx.x & 31, warp = threadIdx.x >> 5;
    int nw = blockDim.x >> 5;
#pragma unroll
    for (int o = 16; o > 0; o >>= 1) v = fmaxf(v, __shfl_down_sync(0xffffffffu, v, o));
    __syncthreads();
    if (lane == 0) sh[warp] = v;
    __syncthreads();
    if (threadIdx.x == 0) {
        float r = sh[0];
        for (int w = 1; w < nw; w++) r = fmaxf(r, sh[w]);
        sh[0] = r;
    }
    __syncthreads();
    return sh[0];
}

__device__ __forceinline__ void discard_l2(const void* p) {
    unsigned long long g;
    asm("cvta.to.global.u64 %0, %1;" : "=l"(g) : "l"(p));
    asm volatile("discard.global.L2 [%0], 128;" :: "l"(g) : "memory");
}

// ---------------- pass 1: short tiles (R7, measured 21.6us) ------------------
template <int Cc, int HWc, int NC, int NH>
__device__ __forceinline__ void pass1_tile(
    const float* __restrict__ s, const float* __restrict__ t,
    __half* __restrict__ dst,
    float* __restrict__ Gsp_s, float* __restrict__ Gsp_t,
    float* __restrict__ Gcp_s, float* __restrict__ Gcp_t,
    float2 (*stage)[TPB], int tile)
{
    const int tid = threadIdx.x;
    const int lane = tid & 31, warp = tid >> 5;
    const int b  = tile / (NC * NH);
    const int r  = tile % (NC * NH);
    const int cc = r / NH;
    const int hh = r % NH;
    const int hwbase = hh * HWCH;
    const int c0 = cc * CCH;

    const size_t base4 = (((size_t)b * Cc + c0) * HWc + hwbase) / 4;
    const float4* ps = (const float4*)s + base4 + tid;
    const float4* pt = (const float4*)t + base4 + tid;
    uint2* pd = (uint2*)dst + base4 + tid;
    constexpr int STR4 = HWc / 4;

    float4 as = make_float4(0.f, 0.f, 0.f, 0.f);
    float4 at = make_float4(0.f, 0.f, 0.f, 0.f);

#pragma unroll
    for (int ci = 0; ci < CCH; ci++) {
        float4 vs = __ldcs(&ps[(size_t)ci * STR4]);   // evict-first
        float4 vt = __ldcs(&pt[(size_t)ci * STR4]);

        __half2 h01 = __floats2half2_rn(vs.x - vt.x, vs.y - vt.y);
        __half2 h23 = __floats2half2_rn(vs.z - vt.z, vs.w - vt.w);
        uint2 u;
        u.x = *reinterpret_cast<const unsigned*>(&h01);
        u.y = *reinterpret_cast<const unsigned*>(&h23);
        pd[(size_t)ci * STR4] = u;

        vs.x = fabsf(vs.x); vs.y = fabsf(vs.y); vs.z = fabsf(vs.z); vs.w = fabsf(vs.w);
        vt.x = fabsf(vt.x); vt.y = fabsf(vt.y); vt.z = fabsf(vt.z); vt.w = fabsf(vt.w);
        as.x += vs.x; as.y += vs.y; as.z += vs.z; as.w += vs.w;
        at.x += vt.x; at.y += vt.y; at.z += vt.z; at.w += vt.w;

        stage[ci][tid] = make_float2((vs.x + vs.y) + (vs.z + vs.w),
                                     (vt.x + vt.y) + (vt.z + vt.w));
    }

    float4* os = (float4*)(Gsp_s + (size_t)cc * (B * HWc) + b * HWc + hwbase) + tid;
    float4* ot = (float4*)(Gsp_t + (size_t)cc * (B * HWc) + b * HWc + hwbase) + tid;
    *os = as;
    *ot = at;

    __syncthreads();

    float2 acc = make_float2(0.f, 0.f);
#pragma unroll
    for (int k = 0; k < TPB / 32; k++) {
        float2 v = stage[warp][lane + 32 * k];
        acc.x += v.x; acc.y += v.y;
    }
    F2D u2; u2.f2 = acc;
#pragma unroll
    for (int o = 16; o > 0; o >>= 1) {
        F2D v; v.d = __shfl_down_sync(0xffffffffu, u2.d, o);
        u2.f2.x += v.f2.x; u2.f2.y += v.f2.y;
    }
    if (lane == 0) {
        int idx = (b * Cc + c0 + warp) * NH + hh;
        Gcp_s[idx] = u2.f2.x;
        Gcp_t[idx] = u2.f2.y;
    }
}

__global__ void __launch_bounds__(TPB, 6)
pass1_kernel(const float* __restrict__ s1, const float* __restrict__ t1,
             const float* __restrict__ s2, const float* __restrict__ t2) {
    __shared__ float2 stage[CCH][TPB];   // 16 KB
    int bid = blockIdx.x;
    if (bid < TILES1)
        pass1_tile<C1, HW1, NC1, NH1>(s1, t1, g_d1,
            &g_Gs1p[0][0][0], &g_Gs1p[1][0][0],
            &g_Gc1p[0][0][0], &g_Gc1p[1][0][0], stage, bid);
    else
        pass1_tile<C2, HW2, NC2, NH2>(s2, t2, g_d2,
            &g_Gs2p[0][0][0], &g_Gs2p[1][0][0],
            &g_Gc2p[0][0][0], &g_Gc2p[1][0][0], stage, bid - TILES1);
}

// ---------------- reduce kernel: Gs partials -> compact, then discard --------
__global__ void reduce_kernel() {
    const unsigned NT = (unsigned)gridDim.x * TPB;
    const unsigned gt = blockIdx.x * TPB + threadIdx.x;

    for (unsigned i = gt; i < B * HW1; i += NT) {
        float ss = 0.f, st = 0.f;
#pragma unroll
        for (int p = 0; p < NC1; p++) { ss += g_Gs1p[0][p][i]; st += g_Gs1p[1][p][i]; }
        g_Gs1[0][i] = ss; g_Gs1[1][i] = st;
    }
    for (unsigned i = gt; i < B * HW2; i += NT) {
        float ss = 0.f, st = 0.f;
#pragma unroll
        for (int p = 0; p < NC2; p++) { ss += g_Gs2p[0][p][i]; st += g_Gs2p[1][p][i]; }
        g_Gs2[0][i] = ss; g_Gs2[1][i] = st;
    }
    __syncthreads();   // this block's reads complete before discarding its lines

    // discard this block's own i-chunks (block-exclusive 128B lines, all p)
    for (unsigned i0 = blockIdx.x * TPB; i0 < B * HW1; i0 += NT) {
        unsigned li = i0 + (threadIdx.x & 31) * 0 + threadIdx.x;   // thread-linear
        // 256 threads cover 256 floats = 8 lines per p; use 8 threads' worth:
        if ((li & 31) == 0) {
#pragma unroll
            for (int p = 0; p < NC1; p++) {
                discard_l2(&g_Gs1p[0][p][li]);
                discard_l2(&g_Gs1p[1][p][li]);
            }
        }
    }
    for (unsigned i0 = blockIdx.x * TPB; i0 < B * HW2; i0 += NT) {
        unsigned li = i0 + threadIdx.x;
        if ((li & 31) == 0) {
#pragma unroll
            for (int p = 0; p < NC2; p++) {
                discard_l2(&g_Gs2p[0][p][li]);
                discard_l2(&g_Gs2p[1][p][li]);
            }
        }
    }
}

// ---------------- softmax + lat (16 blocks; compact Gs) ----------------------
template <int Cc, int HWc, int NPART>
__device__ __forceinline__ void softmax_level(
    const float* __restrict__ Gs_s, const float* __restrict__ Gs_t,
    const float* __restrict__ Gcp_s, const float* __restrict__ Gcp_t,
    float* __restrict__ Ms, float* __restrict__ Mc,
    int b, float* zbuf, double* latout)
{
    const int tid = threadIdx.x;

    float latp = 0.f, mx = -INFINITY;
    for (int i = tid; i < HWc; i += STPB) {
        float ss = Gs_s[b * HWc + i];
        float st = Gs_t[b * HWc + i];
        float d = ss - st;
        latp += d * d;
        float z = (ss + st) * (2.0f / (float)Cc);   // /C then /T (T=0.5)
        zbuf[i] = z;
        mx = fmaxf(mx, z);
    }
    float m = blockReduceMax(mx);
    float se = 0.f;
    for (int i = tid; i < HWc; i += STPB) {
        float e = __expf(zbuf[i] - m);
        zbuf[i] = e;
        se += e;
    }
    float S = blockReduceSum(se);
    float sc = (float)HWc / S;
    for (int i = tid; i < HWc; i += STPB) Ms[b * HWc + i] = zbuf[i] * sc;
    float lat_s = blockReduceSum(latp);

    float latc = 0.f, mxc = -INFINITY;
    for (int i = tid; i < Cc; i += STPB) {
        float cs = 0.f, ct = 0.f;
#pragma unroll
        for (int k = 0; k < NPART; k++) {
            cs += Gcp_s[(size_t)(b * Cc + i) * NPART + k];
            ct += Gcp_t[(size_t)(b * Cc + i) * NPART + k];
        }
        float d = cs - ct;
        latc += d * d;
        float z = (cs + ct) * (2.0f / (float)HWc);
        zbuf[i] = z;
        mxc = fmaxf(mxc, z);
    }
    float m2 = blockReduceMax(mxc);
    float sec = 0.f;
    for (int i = tid; i < Cc; i += STPB) {
        float e = __expf(zbuf[i] - m2);
        zbuf[i] = e;
        sec += e;
    }
    float Sc = blockReduceSum(sec);
    float scc = (float)Cc / Sc;
    for (int i = tid; i < Cc; i += STPB) Mc[b * Cc + i] = zbuf[i] * scc;
    float lat_c = blockReduceSum(latc);

    if (tid == 0)
        *latout = (double)lat_s / ((double)Cc * (double)Cc) +
                  (double)lat_c / ((double)HWc * (double)HWc);
}

__global__ void softmax_kernel() {
    __shared__ float zbuf[HW1];   // 16 KB
    int bid = blockIdx.x;
    if (bid == 0 && threadIdx.x == 0) g_count = 0;   // reset last-block counter
    if (bid < B)
        softmax_level<C1, HW1, NH1>(g_Gs1[0], g_Gs1[1],
            &g_Gc1p[0][0][0], &g_Gc1p[1][0][0],
            g_Ms1, g_Mc1, bid, zbuf, &g_latpart[bid]);
    else
        softmax_level<C2, HW2, NH2>(g_Gs2[0], g_Gs2[1],
            &g_Gc2p[0][0][0], &g_Gc2p[1][0][0],
            g_Ms2, g_Mc2, bid - B, zbuf, &g_latpart[bid]);
}

// ---------------- pass 2 (R7, fused final) -----------------------------------
template <int Cc, int HWc>
__device__ __forceinline__ float pass2_block(
    const __half* __restrict__ dsrc,
    const float* __restrict__ Ms, const float* __restrict__ Mc,
    int b, int c0, int hwbase)
{
    const int tid = threadIdx.x;
    float4 ms = *(const float4*)(Ms + (size_t)b * HWc + hwbase + tid * 4);

    float acc = 0.f;
#pragma unroll
    for (int ci = 0; ci < P2CH; ci++) {
        const int c = c0 + ci;
        const uint2* p = (const uint2*)dsrc +
                         (((size_t)b * Cc + c) * HWc + hwbase) / 4 + tid;
        uint2 v = *p;
        float2 f0 = __half22float2(*reinterpret_cast<const __half2*>(&v.x));
        float2 f1 = __half22float2(*reinterpret_cast<const __half2*>(&v.y));
        float e = f0.x * f0.x * ms.x + f0.y * f0.y * ms.y
                + f1.x * f1.x * ms.z + f1.y * f1.y * ms.w;
        acc += e * Mc[b * Cc + c];
    }
    return acc;
}

template <int Cc, int HWc>
__device__ __forceinline__ void pass2_discard_block(
    const __half* dsrc, int b, int c0, int hwbase)
{
    const int ci = threadIdx.x >> 4;
    const int ln = threadIdx.x & 15;
    const __half* p = dsrc + ((size_t)b * Cc + c0 + ci) * HWc + hwbase + ln * 64;
    discard_l2(p);
}

__global__ void __launch_bounds__(TPB, 6)
pass2_kernel(float* out, int out_size) {
    int bid = blockIdx.x;
    float acc;
    int b, c0, hwbase;
    if (bid < P2B1) {
        b = bid / ((C1 / P2CH) * (HW1 / HWCH));
        int r = bid % ((C1 / P2CH) * (HW1 / HWCH));
        c0 = (r / (HW1 / HWCH)) * P2CH;
        hwbase = (r % (HW1 / HWCH)) * HWCH;
        acc = pass2_block<C1, HW1>(g_d1, g_Ms1, g_Mc1, b, c0, hwbase);
    } else {
        int id = bid - P2B1;
        b = id / (C2 / P2CH);
        c0 = (id % (C2 / P2CH)) * P2CH;
        hwbase = 0;
        acc = pass2_block<C2, HW2>(g_d2, g_Ms2, g_Mc2, b, c0, hwbase);
    }
    float bl = blockReduceSum(acc);   // barrier: block's stash reads complete

    if (bid < P2B1) pass2_discard_block<C1, HW1>(g_d1, b, c0, hwbase);
    else            pass2_discard_block<C2, HW2>(g_d2, b, c0, hwbase);

    __shared__ bool isLast;
    if (threadIdx.x == 0) {
        g_p2[bid] = bl;
        __threadfence();
        unsigned old = atomicAdd(&g_count, 1u);
        isLast = (old == P2TOT - 1);
    }
    __syncthreads();
    if (!isLast) return;

    __threadfence();
    int tid = threadIdx.x;
    double a1 = 0.0, a2 = 0.0;
    for (int i = tid; i < P2B1; i += TPB) a1 += (double)g_p2[i];
    for (int i = P2B1 + tid; i < P2TOT; i += TPB) a2 += (double)g_p2[i];

    __shared__ double sh1[32], sh2[32];
    int lane = tid & 31, warp = tid >> 5;
#pragma unroll
    for (int o = 16; o > 0; o >>= 1) {
        a1 += __shfl_down_sync(0xffffffffu, a1, o);
        a2 += __shfl_down_sync(0xffffffffu, a2, o);
    }
    if (lane == 0) { sh1[warp] = a1; sh2[warp] = a2; }
    __syncthreads();
    if (tid == 0) {
        double s1 = 0.0, s2 = 0.0;
        for (int w = 0; w < TPB / 32; w++) { s1 += sh1[w]; s2 += sh2[w]; }
        double lat = 0.0;
        for (int i = 0; i < 16; i++) lat += g_latpart[i];
        double lam = sqrt(s1) + sqrt(s2);
        double att = (4e-4 * lat + 2e-2 * lam) / (double)B / 2.0;   // ATT=1
        out[0] = (float)(att * (double)B);
        if (out_size > 1) out[1] = (float)att;
    }
}

// ---------------- launch ------------------------------------------------------
extern "C" void kernel_launch(void* const* d_in, const int* in_sizes, int n_in,
                              void* d_out, int out_size) {
    const float* stu1 = (const float*)d_in[1];
    const float* tea1 = (const float*)d_in[2];
    const float* stu2 = (const float*)d_in[3];
    const float* tea2 = (const float*)d_in[4];
    float* out = (float*)d_out;

    pass1_kernel<<<TILES1 + TILES2, TPB>>>(stu1, tea1, stu2, tea2);
    reduce_kernel<<<RGRID, TPB>>>();
    softmax_kernel<<<16, STPB>>>();
    pass2_kernel<<<P2TOT, TPB>>>(out, out_size);
}